// round 10
// baseline (speedup 1.0000x reference)
#include <cuda_runtime.h>
#include <math.h>

#define HH 1024
#define WW 1024
#define NPIX (HH * WW)
#define NBLK 148
#define NTHR 1024
#define SPB 14                     // rows per strip (74 strips >= 1024 rows)
#define SPI 74                     // strips (blocks) per image
#define PPT 4
#define HALF (NPIX / PPT)          // thread-tasks per image in phase 2
#define T2 (2 * HALF)
#define WROW 32                    // bitmask words per row

__device__ unsigned int   g_feat[2][HH * WROW]; // feature bitmask per row
__device__ unsigned short g_g[2][NPIX];         // row 1D distance (0xFFFF = featureless row)
__device__ float          g_sums[2];
__device__ unsigned int   g_count;              // finalize ticket
__device__ unsigned int   g_bar;                // global phase barrier

__device__ __forceinline__ unsigned int hand3(unsigned int w, unsigned int wl, unsigned int wr) {
    // bit b: w[b] & w[b-1] & w[b+1], with cross-word carries
    return w & ((w << 1) | (wl >> 31)) & ((w >> 1) | (wr << 31));
}

__global__ void __launch_bounds__(NTHR, 1) boundary_loss_kernel(
        const float* __restrict__ preds, const float* __restrict__ targets,
        float* __restrict__ out) {
    __shared__ unsigned int sflag[SPB + 2][WROW];
    __shared__ unsigned int sfeat[SPB][WROW];
    __shared__ float warpsum0[NTHR / 32], warpsum1[NTHR / 32];
    int tid = threadIdx.x;
    int wi = tid >> 5, bi = tid & 31;

    // ---------------- Phase 1: edges + row EDT, one strip per block ----------------
    {
        int img   = blockIdx.x / SPI;          // 0 or 1
        int strip = blockIdx.x - img * SPI;    // 0..73
        int y0    = strip * SPB;
        int rows  = min(SPB, HH - y0);
        const float* __restrict__ seg = img ? targets : preds;
        // load flags for strip + halo: one ballot per row
        for (int rr = 0; rr < rows + 2; rr++) {
            int y = y0 + rr - 1;
            bool f = (y >= 0 && y < HH) && (seg[y * WW + tid] == 1.0f);
            unsigned int b = __ballot_sync(0xffffffffu, f);
            if (bi == 0) sflag[rr][wi] = b;
        }
        __syncthreads();
        // erosion for all (row, word) pairs in one parallel step
        if (tid < rows * WROW) {
            int rw = tid >> 5;       // local row
            int wd = tid & 31;       // word
            int rs = rw + 1;
            int y  = y0 + rw;
            unsigned int c = sflag[rs][wd];
            unsigned int er = 0;
            if (y > 0 && y < HH - 1) {
                unsigned int ul = wd ? sflag[rs-1][wd-1] : 0u, ur = (wd < 31) ? sflag[rs-1][wd+1] : 0u;
                unsigned int cl = wd ? sflag[rs  ][wd-1] : 0u, cr = (wd < 31) ? sflag[rs  ][wd+1] : 0u;
                unsigned int dl = wd ? sflag[rs+1][wd-1] : 0u, dr = (wd < 31) ? sflag[rs+1][wd+1] : 0u;
                er = hand3(sflag[rs-1][wd], ul, ur) & hand3(c, cl, cr) & hand3(sflag[rs+1][wd], dl, dr);
                if (wd == 0)  er &= ~1u;           // j = 0 not interior
                if (wd == 31) er &= 0x7FFFFFFFu;   // j = 1023 not interior
            }
            unsigned int fm = c & ~er;
            sfeat[rw][wd] = fm;
            g_feat[img][y * WROW + wd] = fm;
        }
        __syncthreads();
        // row scans: thread tid handles pixel j = tid of each strip row
        for (int rr = 0; rr < rows; rr++) {
            int y = y0 + rr;
            unsigned int self = sfeat[rr][wi];
            unsigned short gv;
            if ((self >> bi) & 1u) {
                gv = 0;
            } else {
                int ld = 1 << 20, rd = 1 << 20;
                unsigned int ml = (bi == 0) ? 0u : (self & (0xFFFFFFFFu >> (32 - bi)));
                if (ml) ld = bi - (31 - __clz(ml));
                else {
                    for (int k = wi - 1; k >= 0; k--) {
                        unsigned int w2 = sfeat[rr][k];
                        if (w2) { ld = (wi - k) * 32 + bi - (31 - __clz(w2)); break; }
                    }
                }
                unsigned int mr = (bi == 31) ? 0u : (self & (0xFFFFFFFEu << bi));
                if (mr) rd = (__ffs(mr) - 1) - bi;
                else {
                    for (int k = wi + 1; k < WROW; k++) {
                        unsigned int w2 = sfeat[rr][k];
                        if (w2) { rd = (k - wi) * 32 + (__ffs(w2) - 1) - bi; break; }
                    }
                }
                int d = min(ld, rd);
                gv = (d >= (1 << 20)) ? (unsigned short)0xFFFF : (unsigned short)d;
            }
            g_g[img][y * WW + tid] = gv;
        }
    }

    // ---------------- Global barrier (all 148 blocks resident) ----------------
    __syncthreads();
    __threadfence();
    if (tid == 0) {
        atomicAdd(&g_bar, 1u);
        while (atomicAdd(&g_bar, 0u) < (unsigned int)NBLK) __nanosleep(64);
    }
    __syncthreads();
    __threadfence();

    // ---------------- Phase 2: column envelope + weighted reduce ----------------
    float val0 = 0.0f, val1 = 0.0f;
    int gtid = blockIdx.x * NTHR + tid;
    for (int t = gtid; t < T2; t += NBLK * NTHR) {
        int img = (t >= HALF);
        int tl  = img ? (t - HALF) : t;
        int idx4 = tl * PPT;
        int i  = idx4 >> 10;
        int j0 = idx4 & (WW - 1);
        unsigned int wmask = g_feat[1 - img][i * WROW + (j0 >> 5)];
        unsigned int wb = (wmask >> (j0 & 31)) & 0xFu;
        if (!wb) continue;
        const unsigned short* __restrict__ gg = g_g[img];
        unsigned char wa[4] = {(unsigned char)(wb & 1u), (unsigned char)((wb >> 1) & 1u),
                               (unsigned char)((wb >> 2) & 1u), (unsigned char)((wb >> 3) & 1u)};
        ushort4 gv4 = *(const ushort4*)&gg[idx4];
        unsigned short ga[4] = {gv4.x, gv4.y, gv4.z, gv4.w};
        float best[4];
        float need = 0.0f;
        #pragma unroll
        for (int c = 0; c < 4; c++) {
            float gf = (ga[c] == 0xFFFFu) ? (1e6f - (float)(j0 + c)) : (float)ga[c];
            best[c] = wa[c] ? gf * gf : 0.0f;
            need = fmaxf(need, best[c]);
        }
        for (int r = 1; r < HH; r++) {
            float rr = (float)(r * r);
            if (rr >= need) break;
            int ku = i - r, kd = i + r;
            if (ku >= 0) {
                ushort4 u4 = *(const ushort4*)&gg[ku * WW + j0];
                unsigned short ua[4] = {u4.x, u4.y, u4.z, u4.w};
                #pragma unroll
                for (int c = 0; c < 4; c++) {
                    float f2 = (ua[c] == 0xFFFFu) ? (1e6f - (float)(j0 + c)) : (float)ua[c];
                    best[c] = fminf(best[c], f2 * f2 + rr);
                }
            }
            if (kd < HH) {
                ushort4 u4 = *(const ushort4*)&gg[kd * WW + j0];
                unsigned short ua[4] = {u4.x, u4.y, u4.z, u4.w};
                #pragma unroll
                for (int c = 0; c < 4; c++) {
                    float f2 = (ua[c] == 0xFFFFu) ? (1e6f - (float)(j0 + c)) : (float)ua[c];
                    best[c] = fminf(best[c], f2 * f2 + rr);
                }
            }
            need = fmaxf(fmaxf(best[0], best[1]), fmaxf(best[2], best[3]));
        }
        float acc = 0.0f;
        #pragma unroll
        for (int c = 0; c < 4; c++)
            if (wa[c]) acc += sqrtf(best[c]);
        if (img) val1 += acc; else val0 += acc;
    }

    // block reduction of both partials
    #pragma unroll
    for (int off = 16; off > 0; off >>= 1) {
        val0 += __shfl_down_sync(0xffffffffu, val0, off);
        val1 += __shfl_down_sync(0xffffffffu, val1, off);
    }
    if (bi == 0) { warpsum0[wi] = val0; warpsum1[wi] = val1; }
    __syncthreads();
    if (wi == 0) {
        val0 = (bi < (NTHR >> 5)) ? warpsum0[bi] : 0.0f;
        val1 = (bi < (NTHR >> 5)) ? warpsum1[bi] : 0.0f;
        #pragma unroll
        for (int off = 16; off > 0; off >>= 1) {
            val0 += __shfl_down_sync(0xffffffffu, val0, off);
            val1 += __shfl_down_sync(0xffffffffu, val1, off);
        }
        if (bi == 0) {
            atomicAdd(&g_sums[0], val0);
            atomicAdd(&g_sums[1], val1);
            __threadfence();
            unsigned int tkt = atomicAdd(&g_count, 1u);
            if (tkt == (unsigned int)(NBLK - 1)) {
                float s0 = atomicAdd(&g_sums[0], 0.0f);
                float s1 = atomicAdd(&g_sums[1], 0.0f);
                float invN = 1.0f / (float)NPIX;
                float loss = (s0 * invN + s1 * invN) * 0.5f;
                out[0] = 1.0f / (1.0f + expf(-loss));
                // reset replay state (all blocks already ticketed past barrier)
                g_sums[0] = 0.0f;
                g_sums[1] = 0.0f;
                g_count = 0u;
                g_bar = 0u;
            }
        }
    }
}

extern "C" void kernel_launch(void* const* d_in, const int* in_sizes, int n_in,
                              void* d_out, int out_size) {
    const float* preds   = (const float*)d_in[0];
    const float* targets = (const float*)d_in[1];
    float* out = (float*)d_out;
    boundary_loss_kernel<<<NBLK, NTHR>>>(preds, targets, out);
}

// round 13
// speedup vs baseline: 1.3367x; 1.3367x over previous
#include <cuda_runtime.h>
#include <math.h>

#define HH 1024
#define WW 1024
#define NPIX (HH * WW)
#define NBLK 148
#define NTHR 1024
#define SPB 14                     // rows per strip in phase 1 (74 strips)
#define SPI 74
#define WROW 32                    // bitmask words per row
#define TCOLS 16                   // columns per phase-2 tile
#define NTILE (2 * (WW / TCOLS))   // 128 tiles
#define SGT_STRIDE 1025            // padded shared stride (f32 elems, odd -> bank-conflict-free)

__device__ unsigned int   g_feat[2][HH * WROW]; // feature bitmask per row
__device__ unsigned short g_g[2][NPIX];         // row 1D distance (0xFFFF = featureless row)
__device__ float          g_sums[2];
__device__ unsigned int   g_count;              // finalize ticket
__device__ unsigned int   g_bar;                // global phase barrier

__device__ __forceinline__ unsigned int hand3(unsigned int w, unsigned int wl, unsigned int wr) {
    return w & ((w << 1) | (wl >> 31)) & ((w >> 1) | (wr << 31));
}

__global__ void __launch_bounds__(NTHR, 1) boundary_loss_kernel(
        const float* __restrict__ preds, const float* __restrict__ targets,
        float* __restrict__ out) {
    __shared__ unsigned int sflag[SPB + 2][WROW];
    __shared__ unsigned int sfeat[SPB][WROW];
    __shared__ float sgt[TCOLS][SGT_STRIDE];    // transposed PRE-SQUARED g2 tile
    __shared__ float warpsum0[NTHR / 32], warpsum1[NTHR / 32];
    int tid = threadIdx.x;
    int wi = tid >> 5, bi = tid & 31;

    // ---------------- Phase 1: edges + row EDT, one strip per block ----------------
    {
        int img   = blockIdx.x / SPI;
        int strip = blockIdx.x - img * SPI;
        int y0    = strip * SPB;
        int rows  = min(SPB, HH - y0);
        const float* __restrict__ seg = img ? targets : preds;
        for (int rr = 0; rr < rows + 2; rr++) {
            int y = y0 + rr - 1;
            bool f = (y >= 0 && y < HH) && (seg[y * WW + tid] == 1.0f);
            unsigned int b = __ballot_sync(0xffffffffu, f);
            if (bi == 0) sflag[rr][wi] = b;
        }
        __syncthreads();
        if (tid < rows * WROW) {
            int rw = tid >> 5, wd = tid & 31;
            int rs = rw + 1;
            int y  = y0 + rw;
            unsigned int c = sflag[rs][wd];
            unsigned int er = 0;
            if (y > 0 && y < HH - 1) {
                unsigned int ul = wd ? sflag[rs-1][wd-1] : 0u, ur = (wd < 31) ? sflag[rs-1][wd+1] : 0u;
                unsigned int cl = wd ? sflag[rs  ][wd-1] : 0u, cr = (wd < 31) ? sflag[rs  ][wd+1] : 0u;
                unsigned int dl = wd ? sflag[rs+1][wd-1] : 0u, dr = (wd < 31) ? sflag[rs+1][wd+1] : 0u;
                er = hand3(sflag[rs-1][wd], ul, ur) & hand3(c, cl, cr) & hand3(sflag[rs+1][wd], dl, dr);
                if (wd == 0)  er &= ~1u;
                if (wd == 31) er &= 0x7FFFFFFFu;
            }
            unsigned int fm = c & ~er;
            sfeat[rw][wd] = fm;
            g_feat[img][y * WROW + wd] = fm;
        }
        __syncthreads();
        for (int rr = 0; rr < rows; rr++) {
            int y = y0 + rr;
            unsigned int self = sfeat[rr][wi];
            unsigned short gv;
            if ((self >> bi) & 1u) {
                gv = 0;
            } else {
                int ld = 1 << 20, rd = 1 << 20;
                unsigned int ml = (bi == 0) ? 0u : (self & (0xFFFFFFFFu >> (32 - bi)));
                if (ml) ld = bi - (31 - __clz(ml));
                else {
                    for (int k = wi - 1; k >= 0; k--) {
                        unsigned int w2 = sfeat[rr][k];
                        if (w2) { ld = (wi - k) * 32 + bi - (31 - __clz(w2)); break; }
                    }
                }
                unsigned int mr = (bi == 31) ? 0u : (self & (0xFFFFFFFEu << bi));
                if (mr) rd = (__ffs(mr) - 1) - bi;
                else {
                    for (int k = wi + 1; k < WROW; k++) {
                        unsigned int w2 = sfeat[rr][k];
                        if (w2) { rd = (k - wi) * 32 + (__ffs(w2) - 1) - bi; break; }
                    }
                }
                int d = min(ld, rd);
                gv = (d >= (1 << 20)) ? (unsigned short)0xFFFF : (unsigned short)d;
            }
            g_g[img][y * WW + tid] = gv;
        }
    }

    // ---------------- Global barrier (all 148 blocks resident, 1 CTA/SM) ------------
    __syncthreads();
    __threadfence();
    if (tid == 0) {
        atomicAdd(&g_bar, 1u);
        while (atomicAdd(&g_bar, 0u) < (unsigned int)NBLK) __nanosleep(64);
    }
    __syncthreads();
    __threadfence();

    // ---------------- Phase 2: column EDT on pre-squared shared tiles --------------
    float val0 = 0.0f, val1 = 0.0f;
    for (int tile = blockIdx.x; tile < NTILE; tile += NBLK) {
        int img = tile >> 6;                 // 0..1
        int j0  = (tile & 63) * TCOLS;       // column band start
        const unsigned short* __restrict__ gg = g_g[img];
        // load band (coalesced row-major), square once, store transposed f32
        for (int idx = tid; idx < HH * (TCOLS / 2); idx += NTHR) {
            int i = idx >> 3;                // row
            int w = idx & 7;                 // uint word within band (2 cols)
            unsigned int v = *(const unsigned int*)&gg[i * WW + j0 + 2 * w];
            unsigned int u0 = v & 0xFFFFu, u1 = v >> 16;
            float f0 = (u0 == 0xFFFFu) ? (1e6f - (float)(j0 + 2 * w))     : (float)u0;
            float f1 = (u1 == 0xFFFFu) ? (1e6f - (float)(j0 + 2 * w + 1)) : (float)u1;
            sgt[2 * w][i]     = f0 * f0;
            sgt[2 * w + 1][i] = f1 * f1;
        }
        __syncthreads();
        int jc = tid & (TCOLS - 1);
        int ir = tid >> 4;                   // 0..63
        int j  = j0 + jc;
        int wsh = j & 31, wwd = j >> 5;
        const float* __restrict__ col = sgt[jc];
        const unsigned int* __restrict__ fo = &g_feat[1 - img][wwd];
        float acc = 0.0f;
        #pragma unroll 4
        for (int q = 0; q < 16; q++) {
            int i = ir + 64 * q;
            if (!((fo[i * WROW] >> wsh) & 1u)) continue;
            float best = col[i];
            for (int r = 1; r < HH; r++) {
                float rr = (float)(r * r);
                if (rr >= best) break;
                int ku = i - r, kd = i + r;
                if (ku >= 0) best = fminf(best, col[ku] + rr);
                if (kd < HH) best = fminf(best, col[kd] + rr);
            }
            acc += sqrtf(best);
        }
        if (img) val1 += acc; else val0 += acc;
        __syncthreads();   // protect sgt before next tile's load
    }

    // block reduction of both partials
    #pragma unroll
    for (int off = 16; off > 0; off >>= 1) {
        val0 += __shfl_down_sync(0xffffffffu, val0, off);
        val1 += __shfl_down_sync(0xffffffffu, val1, off);
    }
    if (bi == 0) { warpsum0[wi] = val0; warpsum1[wi] = val1; }
    __syncthreads();
    if (wi == 0) {
        val0 = (bi < (NTHR >> 5)) ? warpsum0[bi] : 0.0f;
        val1 = (bi < (NTHR >> 5)) ? warpsum1[bi] : 0.0f;
        #pragma unroll
        for (int off = 16; off > 0; off >>= 1) {
            val0 += __shfl_down_sync(0xffffffffu, val0, off);
            val1 += __shfl_down_sync(0xffffffffu, val1, off);
        }
        if (bi == 0) {
            atomicAdd(&g_sums[0], val0);
            atomicAdd(&g_sums[1], val1);
            __threadfence();
            unsigned int tkt = atomicAdd(&g_count, 1u);
            if (tkt == (unsigned int)(NBLK - 1)) {
                float s0 = atomicAdd(&g_sums[0], 0.0f);
                float s1 = atomicAdd(&g_sums[1], 0.0f);
                float invN = 1.0f / (float)NPIX;
                float loss = (s0 * invN + s1 * invN) * 0.5f;
                out[0] = 1.0f / (1.0f + expf(-loss));
                g_sums[0] = 0.0f;
                g_sums[1] = 0.0f;
                g_count = 0u;
                g_bar = 0u;
            }
        }
    }
}

extern "C" void kernel_launch(void* const* d_in, const int* in_sizes, int n_in,
                              void* d_out, int out_size) {
    const float* preds   = (const float*)d_in[0];
    const float* targets = (const float*)d_in[1];
    float* out = (float*)d_out;
    boundary_loss_kernel<<<NBLK, NTHR>>>(preds, targets, out);
}

// round 15
// speedup vs baseline: 1.4396x; 1.0769x over previous
#include <cuda_runtime.h>
#include <math.h>

#define HH 1024
#define WW 1024
#define NPIX (HH * WW)
#define NBLK 148
#define NTHR 1024
#define SPB 14                     // rows per strip in phase 1 (74 strips)
#define SPI 74
#define WROW 32                    // bitmask words per row
#define TCOLS 16                   // columns per phase-2 tile
#define NTILE (2 * (WW / TCOLS))   // 128 tiles
#define SGT_STRIDE 1025            // padded shared stride (f32, odd -> conflict-free)

__device__ unsigned int   g_feat[2][HH * WROW]; // feature bitmask per row
__device__ unsigned short g_g[2][NPIX];         // row 1D distance (0xFFFF = featureless row)
__device__ float          g_sums[2];
__device__ unsigned int   g_count;              // finalize ticket
__device__ unsigned int   g_bar;                // global phase barrier

__device__ __forceinline__ unsigned int hand3(unsigned int w, unsigned int wl, unsigned int wr) {
    return w & ((w << 1) | (wl >> 31)) & ((w >> 1) | (wr << 31));
}

__global__ void __launch_bounds__(NTHR, 1) boundary_loss_kernel(
        const float* __restrict__ preds, const float* __restrict__ targets,
        float* __restrict__ out) {
    __shared__ unsigned int sflag[SPB + 2][WROW];
    __shared__ unsigned int sfeat[SPB][WROW];
    __shared__ float sgt[TCOLS][SGT_STRIDE];    // transposed PRE-SQUARED g2 tile
    __shared__ float warpsum0[NTHR / 32], warpsum1[NTHR / 32];
    int tid = threadIdx.x;
    int wi = tid >> 5, bi = tid & 31;

    // ---------------- Phase 1: edges + row EDT, one strip per block ----------------
    {
        int img   = blockIdx.x / SPI;
        int strip = blockIdx.x - img * SPI;
        int y0    = strip * SPB;
        int rows  = min(SPB, HH - y0);
        const float* __restrict__ seg = img ? targets : preds;
        for (int rr = 0; rr < rows + 2; rr++) {
            int y = y0 + rr - 1;
            bool f = (y >= 0 && y < HH) && (seg[y * WW + tid] == 1.0f);
            unsigned int b = __ballot_sync(0xffffffffu, f);
            if (bi == 0) sflag[rr][wi] = b;
        }
        __syncthreads();
        if (tid < rows * WROW) {
            int rw = tid >> 5, wd = tid & 31;
            int rs = rw + 1;
            int y  = y0 + rw;
            unsigned int c = sflag[rs][wd];
            unsigned int er = 0;
            if (y > 0 && y < HH - 1) {
                unsigned int ul = wd ? sflag[rs-1][wd-1] : 0u, ur = (wd < 31) ? sflag[rs-1][wd+1] : 0u;
                unsigned int cl = wd ? sflag[rs  ][wd-1] : 0u, cr = (wd < 31) ? sflag[rs  ][wd+1] : 0u;
                unsigned int dl = wd ? sflag[rs+1][wd-1] : 0u, dr = (wd < 31) ? sflag[rs+1][wd+1] : 0u;
                er = hand3(sflag[rs-1][wd], ul, ur) & hand3(c, cl, cr) & hand3(sflag[rs+1][wd], dl, dr);
                if (wd == 0)  er &= ~1u;
                if (wd == 31) er &= 0x7FFFFFFFu;
            }
            unsigned int fm = c & ~er;
            sfeat[rw][wd] = fm;
            g_feat[img][y * WROW + wd] = fm;
        }
        __syncthreads();
        // row scans: u64 windows -> straight-line clz/ffs (fallback ~never taken)
        for (int rr = 0; rr < rows; rr++) {
            int y = y0 + rr;
            unsigned int self = sfeat[rr][wi];
            unsigned short gv;
            if ((self >> bi) & 1u) {
                gv = 0;
            } else {
                unsigned int wl = wi ? sfeat[rr][wi - 1] : 0u;
                unsigned int wr = (wi < WROW - 1) ? sfeat[rr][wi + 1] : 0u;
                int ld = 1 << 20, rd = 1 << 20;
                // left: 64-bit window [left word | self], pos p = 32 + bi
                unsigned long long vl = ((unsigned long long)self << 32) | wl;
                unsigned long long ml = vl & ((1ULL << (32 + bi)) - 1ULL);
                if (ml) {
                    ld = (32 + bi) - (63 - __clzll(ml));
                } else {
                    for (int k = wi - 2; k >= 0; k--) {
                        unsigned int w2 = sfeat[rr][k];
                        if (w2) { ld = (wi - k) * 32 + bi - (31 - __clz(w2)); break; }
                    }
                }
                // right: 64-bit window [right word | self], pos = bi
                unsigned long long vr = ((unsigned long long)wr << 32) | self;
                unsigned long long mr = vr & (~0ULL << (bi + 1));
                if (mr) {
                    rd = (__ffsll(mr) - 1) - bi;
                } else {
                    for (int k = wi + 2; k < WROW; k++) {
                        unsigned int w2 = sfeat[rr][k];
                        if (w2) { rd = (k - wi) * 32 + (__ffs(w2) - 1) - bi; break; }
                    }
                }
                int d = min(ld, rd);
                gv = (d >= (1 << 20)) ? (unsigned short)0xFFFF : (unsigned short)d;
            }
            g_g[img][y * WW + tid] = gv;
        }
    }

    // ---------------- Global barrier (all 148 blocks resident, 1 CTA/SM) ------------
    __syncthreads();
    __threadfence();
    if (tid == 0) {
        atomicAdd(&g_bar, 1u);
        while (atomicAdd(&g_bar, 0u) < (unsigned int)NBLK) __nanosleep(64);
    }
    __syncthreads();
    __threadfence();

    // ---------------- Phase 2: column EDT on pre-squared shared tiles --------------
    float val0 = 0.0f, val1 = 0.0f;
    for (int tile = blockIdx.x; tile < NTILE; tile += NBLK) {
        int img = tile >> 6;
        int j0  = (tile & 63) * TCOLS;
        const unsigned short* __restrict__ gg = g_g[img];
        for (int idx = tid; idx < HH * (TCOLS / 2); idx += NTHR) {
            int i = idx >> 3;
            int w = idx & 7;
            unsigned int v = *(const unsigned int*)&gg[i * WW + j0 + 2 * w];
            unsigned int u0 = v & 0xFFFFu, u1 = v >> 16;
            float f0 = (u0 == 0xFFFFu) ? (1e6f - (float)(j0 + 2 * w))     : (float)u0;
            float f1 = (u1 == 0xFFFFu) ? (1e6f - (float)(j0 + 2 * w + 1)) : (float)u1;
            sgt[2 * w][i]     = f0 * f0;
            sgt[2 * w + 1][i] = f1 * f1;
        }
        __syncthreads();
        int jc = tid & (TCOLS - 1);
        int ir = tid >> 4;
        int j  = j0 + jc;
        int wsh = j & 31, wwd = j >> 5;
        const float* __restrict__ col = sgt[jc];
        const unsigned int* __restrict__ fo = &g_feat[1 - img][wwd];
        float acc = 0.0f;
        #pragma unroll 4
        for (int q = 0; q < 16; q++) {
            int i = ir + 64 * q;
            if (!((fo[i * WROW] >> wsh) & 1u)) continue;
            float best = col[i];
            float rrf = 1.0f, dstep = 3.0f;   // rrf = r^2 via exact integer f32 adds
            for (int r = 1; r < HH; r++) {
                if (rrf >= best) break;
                int ku = i - r, kd = i + r;
                if (ku >= 0) best = fminf(best, col[ku] + rrf);
                if (kd < HH) best = fminf(best, col[kd] + rrf);
                rrf += dstep; dstep += 2.0f;
            }
            float s;
            asm("sqrt.approx.f32 %0, %1;" : "=f"(s) : "f"(best));
            acc += s;
        }
        if (img) val1 += acc; else val0 += acc;
        __syncthreads();
    }

    // block reduction of both partials
    #pragma unroll
    for (int off = 16; off > 0; off >>= 1) {
        val0 += __shfl_down_sync(0xffffffffu, val0, off);
        val1 += __shfl_down_sync(0xffffffffu, val1, off);
    }
    if (bi == 0) { warpsum0[wi] = val0; warpsum1[wi] = val1; }
    __syncthreads();
    if (wi == 0) {
        val0 = (bi < (NTHR >> 5)) ? warpsum0[bi] : 0.0f;
        val1 = (bi < (NTHR >> 5)) ? warpsum1[bi] : 0.0f;
        #pragma unroll
        for (int off = 16; off > 0; off >>= 1) {
            val0 += __shfl_down_sync(0xffffffffu, val0, off);
            val1 += __shfl_down_sync(0xffffffffu, val1, off);
        }
        if (bi == 0) {
            atomicAdd(&g_sums[0], val0);
            atomicAdd(&g_sums[1], val1);
            __threadfence();
            unsigned int tkt = atomicAdd(&g_count, 1u);
            if (tkt == (unsigned int)(NBLK - 1)) {
                float s0 = atomicAdd(&g_sums[0], 0.0f);
                float s1 = atomicAdd(&g_sums[1], 0.0f);
                float invN = 1.0f / (float)NPIX;
                float loss = (s0 * invN + s1 * invN) * 0.5f;
                out[0] = 1.0f / (1.0f + expf(-loss));
                g_sums[0] = 0.0f;
                g_sums[1] = 0.0f;
                g_count = 0u;
                g_bar = 0u;
            }
        }
    }
}

extern "C" void kernel_launch(void* const* d_in, const int* in_sizes, int n_in,
                              void* d_out, int out_size) {
    const float* preds   = (const float*)d_in[0];
    const float* targets = (const float*)d_in[1];
    float* out = (float*)d_out;
    boundary_loss_kernel<<<NBLK, NTHR>>>(preds, targets, out);
}